// round 12
// baseline (speedup 1.0000x reference)
#include <cuda_runtime.h>
#include <cuda_bf16.h>
#include <math.h>
#include <cstdint>

// InfoNCE loss. B=16384, D=256, T=0.07. bf16 mma.sync path (compute_103-safe).
// Persistent row-tile CTAs (128), 512 threads / 16 warps (32x32 per warp).
// A(q) tile loaded once; B(d) tiles streamed, cp.async double-buffered.
// q pre-scaled by log2(e)/T so the epilogue is pure ex2.approx; fixed shift
// M2 = log2(e)/T >= any scaled sim -> stable LSE, no atomics, deterministic.
// sim (1 GB) never materialized.

#define B_N 16384
#define D_K 256
#define NT  128
#define LOG2E 1.4426950408889634f
#define LN2   0.6931471805599453f
#define M2_SHIFT (14.285714285714286f * LOG2E)   // (1/T) * log2(e)

static __device__ __nv_bfloat16 g_qb[B_N * D_K];   // q-hat * log2e/T
static __device__ __nv_bfloat16 g_db[B_N * D_K];   // d-hat
static __device__ float g_diag[B_N];               // diag in log2 units
static __device__ float g_rowsum[B_N];
static __device__ float g_colpart[NT * B_N];       // [rowTile][col]
static __device__ float g_blockRow[64];
static __device__ float g_blockCol[64];

// ---------------- PTX helpers (plain sm_103-safe) --------------------------
__device__ __forceinline__ uint32_t smem_u32(const void* p) {
    uint32_t a;
    asm("{ .reg .u64 t; cvta.to.shared.u64 t, %1; cvt.u32.u64 %0, t; }" : "=r"(a) : "l"(p));
    return a;
}
__device__ __forceinline__ void cp16(uint32_t dst, const void* src) {
    asm volatile("cp.async.cg.shared.global [%0], [%1], 16;" :: "r"(dst), "l"(src) : "memory");
}
#define CP_COMMIT() asm volatile("cp.async.commit_group;" ::: "memory")
#define CP_WAIT(n)  asm volatile("cp.async.wait_group %0;" :: "n"(n) : "memory")

__device__ __forceinline__ float ex2(float x) {
    float r; asm("ex2.approx.ftz.f32 %0, %1;" : "=f"(r) : "f"(x)); return r;
}

#define LDSM4(r0, r1, r2, r3, addr)                                          \
    asm volatile("ldmatrix.sync.aligned.m8n8.x4.shared.b16 {%0,%1,%2,%3}, [%4];" \
        : "=r"(r0), "=r"(r1), "=r"(r2), "=r"(r3) : "r"(addr))

#define MMA16816(c, a, b)                                                    \
    asm volatile("mma.sync.aligned.m16n8k16.row.col.f32.bf16.bf16.f32 "      \
        "{%0,%1,%2,%3}, {%4,%5,%6,%7}, {%8,%9}, {%0,%1,%2,%3};"              \
        : "+f"((c)[0]), "+f"((c)[1]), "+f"((c)[2]), "+f"((c)[3])             \
        : "r"((a)[0]), "r"((a)[1]), "r"((a)[2]), "r"((a)[3]),                \
          "r"((b)[0]), "r"((b)[1]))

// ---------------------------------------------------------------------------
// 1. Normalize -> bf16. q scaled by log2e/T. One warp per row.
// ---------------------------------------------------------------------------
__global__ void normalize_kernel(const float* __restrict__ in, int is_q) {
    int warp = threadIdx.x >> 5;
    int lane = threadIdx.x & 31;
    int row  = blockIdx.x * 8 + warp;
    const float* src = in + (size_t)row * D_K;
    float v[8];
    float s = 0.f;
#pragma unroll
    for (int j = 0; j < 8; ++j) { v[j] = src[j * 32 + lane]; s += v[j] * v[j]; }
#pragma unroll
    for (int o = 16; o > 0; o >>= 1) s += __shfl_xor_sync(0xffffffffu, s, o);
    float extra = is_q ? (LOG2E / 0.07f) : 1.0f;
    float scale = extra / fmaxf(sqrtf(s), 1e-12f);
    __nv_bfloat16* dst = (is_q ? g_qb : g_db) + (size_t)row * D_K;
#pragma unroll
    for (int j = 0; j < 8; ++j) dst[j * 32 + lane] = __float2bfloat16(v[j] * scale);
}

// ---------------------------------------------------------------------------
// 2. diag[i] = qb_i . db_i  (log2-scaled units; matches GEMM inputs)
// ---------------------------------------------------------------------------
__global__ void diag_kernel() {
    int warp = threadIdx.x >> 5;
    int lane = threadIdx.x & 31;
    int row  = blockIdx.x * 8 + warp;
    const __nv_bfloat16* a = g_qb + (size_t)row * D_K;
    const __nv_bfloat16* b = g_db + (size_t)row * D_K;
    float s = 0.f;
#pragma unroll
    for (int j = 0; j < 8; ++j) {
        int c = j * 32 + lane;
        s += __bfloat162float(a[c]) * __bfloat162float(b[c]);
    }
#pragma unroll
    for (int o = 16; o > 0; o >>= 1) s += __shfl_xor_sync(0xffffffffu, s, o);
    if (lane == 0) g_diag[row] = s;
}

// ---------------------------------------------------------------------------
// 3. Persistent GEMM + exp2 partials. Grid 128 (row tiles), 512 threads.
//    Warp grid 4x4: warp = 32 rows x 32 cols (mt 2 x nt 4 m16n8k16 frags).
//    SMEM: A 64K @0, B buf0 @65536, B buf1 @131072, colred 2K, rowred 2K.
//    Tile layout: [row][16B chunk c], 32 chunks/row, swizzle c ^= (row & 7).
// ---------------------------------------------------------------------------
#define SMEM_B0     65536
#define SMEM_B1     131072
#define SMEM_COLRED 196608
#define SMEM_ROWRED 198656
#define SMEM_SZ     200704

__device__ __forceinline__ void load_tile(uint32_t dstBase,
                                          const __nv_bfloat16* src, int tid) {
#pragma unroll
    for (int it = 0; it < 8; ++it) {
        int e = it * 512 + tid;          // 0..4095
        int r = e >> 5, c = e & 31;      // row, 16B chunk (full K=256)
        cp16(dstBase + r * 512 + ((c ^ (r & 7)) << 4),
             (const char*)(src + (size_t)r * D_K) + c * 16);
    }
}

__global__ __launch_bounds__(512, 1) void gemm_lse_kernel() {
    extern __shared__ char smem[];
    uint32_t sb = smem_u32(smem);
    int tid = threadIdx.x;
    int lane = tid & 31;
    int wid  = tid >> 5;
    int wr = wid >> 2;         // warp row (0..3) -> 32 rows each
    int wc = wid & 3;          // warp col (0..3) -> 32 cols each
    int rowBase = blockIdx.x * 128;

    // A (q rows) once; B tile 0 prefetch.
    load_tile(sb, g_qb + (size_t)rowBase * D_K, tid);
    CP_COMMIT();
    load_tile(sb + SMEM_B0, g_db, tid);
    CP_COMMIT();

    // per-lane ldmatrix row/chunk components
    int aRowL   = wr * 32 + (lane & 15);                          // + mt*16
    int aChunkL = lane >> 4;                                      // + 2*ks
    int bRowL   = wc * 32 + ((lane >> 4) & 1) * 8 + (lane & 7);   // + p*16
    int bChunkL = (lane >> 3) & 1;                                // + 2*ks

    // row partials accumulate across ALL col tiles (registers)
    float rp0[2], rp1[2];
    rp0[0] = rp0[1] = rp1[0] = rp1[1] = 0.f;

    float* colred = (float*)(smem + SMEM_COLRED);   // [128][4]

#pragma unroll 1
    for (int t = 0; t < NT; ++t) {
        if (t + 1 < NT) {
            load_tile(sb + (((t + 1) & 1) ? SMEM_B1 : SMEM_B0),
                      g_db + (size_t)(t + 1) * 128 * D_K, tid);
            CP_COMMIT();
            CP_WAIT(1);
        } else {
            CP_WAIT(0);
        }
        __syncthreads();

        float acc[2][4][4];
#pragma unroll
        for (int mt = 0; mt < 2; ++mt)
#pragma unroll
            for (int nt = 0; nt < 4; ++nt)
#pragma unroll
                for (int k = 0; k < 4; ++k) acc[mt][nt][k] = 0.f;

        uint32_t bBase = sb + ((t & 1) ? SMEM_B1 : SMEM_B0);
#pragma unroll
        for (int ks = 0; ks < 16; ++ks) {
            uint32_t a[2][4];
#pragma unroll
            for (int mt = 0; mt < 2; ++mt) {
                int rrow = aRowL + mt * 16;
                int cc = 2 * ks + aChunkL;
                uint32_t ad = sb + rrow * 512 + ((cc ^ (rrow & 7)) << 4);
                LDSM4(a[mt][0], a[mt][1], a[mt][2], a[mt][3], ad);
            }
            uint32_t b[4][2];
#pragma unroll
            for (int p = 0; p < 2; ++p) {
                int rrow = bRowL + p * 16;
                int cc = 2 * ks + bChunkL;
                uint32_t bd = bBase + rrow * 512 + ((cc ^ (rrow & 7)) << 4);
                uint32_t r0, r1, r2, r3;
                LDSM4(r0, r1, r2, r3, bd);
                b[2 * p][0] = r0; b[2 * p][1] = r1;
                b[2 * p + 1][0] = r2; b[2 * p + 1][1] = r3;
            }
#pragma unroll
            for (int mt = 0; mt < 2; ++mt)
#pragma unroll
                for (int nt = 0; nt < 4; ++nt) MMA16816(acc[mt][nt], a[mt], b[nt]);
        }

        // ---- epilogue: ex2(sim2 - M2); rows -> registers, cols -> smem ----
        float cq0[4], cq1[4];
#pragma unroll
        for (int i = 0; i < 4; ++i) { cq0[i] = cq1[i] = 0.f; }
#pragma unroll
        for (int mt = 0; mt < 2; ++mt)
#pragma unroll
            for (int nt = 0; nt < 4; ++nt) {
                float e0 = ex2(acc[mt][nt][0] - M2_SHIFT);
                float e1 = ex2(acc[mt][nt][1] - M2_SHIFT);
                float e2 = ex2(acc[mt][nt][2] - M2_SHIFT);
                float e3 = ex2(acc[mt][nt][3] - M2_SHIFT);
                rp0[mt] += e0 + e1;
                rp1[mt] += e2 + e3;
                cq0[nt] += e0 + e2;
                cq1[nt] += e1 + e3;
            }
        // col sums: reduce across the 8 lane-groups sharing a col
#pragma unroll
        for (int o = 4; o <= 16; o <<= 1)
#pragma unroll
            for (int nt = 0; nt < 4; ++nt) {
                cq0[nt] += __shfl_xor_sync(0xffffffffu, cq0[nt], o);
                cq1[nt] += __shfl_xor_sync(0xffffffffu, cq1[nt], o);
            }
        if (lane < 4) {
#pragma unroll
            for (int nt = 0; nt < 4; ++nt) {
                int col = wc * 32 + nt * 8 + lane * 2;
                colred[col * 4 + wr]       = cq0[nt];
                colred[(col + 1) * 4 + wr] = cq1[nt];
            }
        }
        __syncthreads();
        if (tid < 128) {
            float cs = colred[tid * 4] + colred[tid * 4 + 1] +
                       colred[tid * 4 + 2] + colred[tid * 4 + 3];
            g_colpart[(size_t)blockIdx.x * B_N + t * 128 + tid] = cs;
        }
    }

    // ---- final row sums (once per CTA) ----
#pragma unroll
    for (int o = 1; o <= 2; o <<= 1)
#pragma unroll
        for (int mt = 0; mt < 2; ++mt) {
            rp0[mt] += __shfl_xor_sync(0xffffffffu, rp0[mt], o);
            rp1[mt] += __shfl_xor_sync(0xffffffffu, rp1[mt], o);
        }
    float* rowred = (float*)(smem + SMEM_ROWRED);   // [128][4]
    __syncthreads();
    if ((lane & 3) == 0) {
        int rloc = wr * 32 + (lane >> 2);
#pragma unroll
        for (int mt = 0; mt < 2; ++mt) {
            rowred[(rloc + mt * 16) * 4 + wc]     = rp0[mt];
            rowred[(rloc + mt * 16 + 8) * 4 + wc] = rp1[mt];
        }
    }
    __syncthreads();
    if (tid < 128) {
        float rs = rowred[tid * 4] + rowred[tid * 4 + 1] +
                   rowred[tid * 4 + 2] + rowred[tid * 4 + 3];
        g_rowsum[rowBase + tid] = rs;
    }
}

// ---------------------------------------------------------------------------
// 4a. Per-row loss terms (log2 domain -> nats) + deterministic tree reduce
// ---------------------------------------------------------------------------
__global__ void finalize1_kernel() {
    int i = blockIdx.x * 256 + threadIdx.x;
    float cs = 0.f;
#pragma unroll 4
    for (int t = 0; t < NT; ++t) cs += g_colpart[(size_t)t * B_N + i];
    float rs = g_rowsum[i];
    float dg = g_diag[i];
    float rw = LN2 * (M2_SHIFT + log2f(rs) - dg);
    float cw = LN2 * (M2_SHIFT + log2f(cs) - dg);

    __shared__ float sr[256], sc[256];
    sr[threadIdx.x] = rw;
    sc[threadIdx.x] = cw;
    __syncthreads();
    for (int o = 128; o > 0; o >>= 1) {
        if (threadIdx.x < o) {
            sr[threadIdx.x] += sr[threadIdx.x + o];
            sc[threadIdx.x] += sc[threadIdx.x + o];
        }
        __syncthreads();
    }
    if (threadIdx.x == 0) {
        g_blockRow[blockIdx.x] = sr[0];
        g_blockCol[blockIdx.x] = sc[0];
    }
}

// 4b. Final scalar
__global__ void finalize2_kernel(float* out) {
    float sR = 0.f, sC = 0.f;
    for (int b = 0; b < 64; ++b) { sR += g_blockRow[b]; sC += g_blockCol[b]; }
    out[0] = (sR + sC) / (2.0f * (float)B_N);
}

// ---------------------------------------------------------------------------
extern "C" void kernel_launch(void* const* d_in, const int* in_sizes, int n_in,
                              void* d_out, int out_size) {
    const float* q = (const float*)d_in[0];
    const float* d = (const float*)d_in[1];
    float* out = (float*)d_out;

    cudaFuncSetAttribute(gemm_lse_kernel,
                         cudaFuncAttributeMaxDynamicSharedMemorySize, SMEM_SZ);

    normalize_kernel<<<B_N / 8, 256>>>(q, 1);
    normalize_kernel<<<B_N / 8, 256>>>(d, 0);
    diag_kernel<<<B_N / 8, 256>>>();
    gemm_lse_kernel<<<NT, 512, SMEM_SZ>>>();
    finalize1_kernel<<<B_N / 256, 256>>>();
    finalize2_kernel<<<1, 1>>>(out);
}